// round 9
// baseline (speedup 1.0000x reference)
#include <cuda_runtime.h>
#include <cuda_fp16.h>
#include <math.h>
#include <stdint.h>

#define N_NODES 50000
#define N_EDGES 800000
#define HID     384
#define DOUT    128
#define TME     128                 // edges per tile
#define NT      (N_EDGES / TME)     // 6250

// ---------------- device scratch ----------------
__device__ __half g_P16[(size_t)N_NODES * HID];   // vc @ W1[0:128]        (fp16)
__device__ __half g_Q16[(size_t)N_NODES * HID];   // vc @ W1[128:256] + b1 (fp16)
__device__ float  g_W23[HID * DOUT];              // W2[:,1:] @ W3
__device__ float  g_w20[HID];                     // W2[:,0]
__device__ float  g_c0[DOUT];                     // b2[1:] @ W3
__device__ float  g_b20;                          // b2[0]

// ---------------- helpers ----------------
__device__ __forceinline__ uint32_t f2tf(float f) {
    uint32_t u; asm("cvt.rna.tf32.f32 %0, %1;" : "=r"(u) : "f"(f)); return u;
}
__device__ __forceinline__ void mma_tf32(float c[4],
        uint32_t a0, uint32_t a1, uint32_t a2, uint32_t a3,
        uint32_t b0, uint32_t b1) {
    asm volatile("mma.sync.aligned.m16n8k8.row.col.f32.tf32.tf32.f32 "
        "{%0,%1,%2,%3}, {%4,%5,%6,%7}, {%8,%9}, {%0,%1,%2,%3};"
        : "+f"(c[0]), "+f"(c[1]), "+f"(c[2]), "+f"(c[3])
        : "r"(a0), "r"(a1), "r"(a2), "r"(a3), "r"(b0), "r"(b1));
}
__device__ __forceinline__ void mma_f16(float c[4],
        uint32_t a0, uint32_t a1, uint32_t a2, uint32_t a3,
        uint32_t b0, uint32_t b1) {
    asm volatile("mma.sync.aligned.m16n8k16.row.col.f32.f16.f16.f32 "
        "{%0,%1,%2,%3}, {%4,%5,%6,%7}, {%8,%9}, {%0,%1,%2,%3};"
        : "+f"(c[0]), "+f"(c[1]), "+f"(c[2]), "+f"(c[3])
        : "r"(a0), "r"(a1), "r"(a2), "r"(a3), "r"(b0), "r"(b1));
}
__device__ __forceinline__ uint32_t f22h2u(float a, float b) {
    __half2 h = __floats2half2_rn(a, b);
    return *reinterpret_cast<uint32_t*>(&h);
}
__device__ __forceinline__ float2 u2f2(uint32_t u) {
    __half2 h = *reinterpret_cast<__half2*>(&u);
    return __half22float2(h);
}
#define WM_BAR(wm) asm volatile("bar.sync %0, 64;" :: "r"((wm) + 1) : "memory")

// ---------------- tiny precompute kernels ----------------
__global__ void k_w23(const float* __restrict__ W2, const float* __restrict__ W3) {
    __shared__ float s[512];
    int k = blockIdx.x, t = threadIdx.x;
    for (int j = t; j < 512; j += 128) s[j] = W2[k * 513 + 1 + j];
    __syncthreads();
    float acc = 0.f;
#pragma unroll 8
    for (int j = 0; j < 512; j++) acc = fmaf(s[j], W3[j * DOUT + t], acc);
    g_W23[k * DOUT + t] = acc;
}
__global__ void k_misc(const float* __restrict__ W2, const float* __restrict__ b2,
                       const float* __restrict__ W3) {
    int t = threadIdx.x;
    if (t < HID) g_w20[t] = W2[t * 513];
    if (t < DOUT) {
        float acc = 0.f;
        for (int j = 0; j < 512; j++) acc = fmaf(b2[1 + j], W3[j * DOUT + t], acc);
        g_c0[t] = acc;
    }
    if (t == 0) g_b20 = b2[0];
}

// ---------------- k_pq (proven) ----------------
#define PQ_TM 32
__global__ void __launch_bounds__(256) k_pq(const float* __restrict__ vc,
                                            const float* __restrict__ W1,
                                            const float* __restrict__ b1) {
    extern __shared__ uint32_t smu[];
    uint32_t* s_w = smu;
    uint32_t* s_x = smu + 128 * 136;
    int t = threadIdx.x;
    int chunk = blockIdx.x;
    int half = chunk / 3, nc = chunk - half * 3;
    int n0t = blockIdx.y * PQ_TM;

    for (int i = t; i < 128 * 128; i += 256) {
        int k = i >> 7, n = i & 127;
        s_w[k * 136 + n] = f2tf(W1[(size_t)(half * 128 + k) * HID + nc * 128 + n]);
    }
    for (int i = t; i < PQ_TM * 128; i += 256) {
        int r = i >> 7, k = i & 127;
        int node = n0t + r; if (node >= N_NODES) node = N_NODES - 1;
        s_x[r * 132 + k] = f2tf(vc[(size_t)node * 128 + k]);
    }
    __syncthreads();
    int warp = t >> 5, lane = t & 31;
    int wm = warp >> 2, wn = warp & 3;
    int g = lane >> 2, tt = lane & 3;
    int mb = wm * 16;
    float acc[4][4];
#pragma unroll
    for (int j = 0; j < 4; j++) {
        int col = nc * 128 + wn * 32 + j * 8 + 2 * tt;
        float bv0 = half ? b1[col] : 0.f;
        float bv1 = half ? b1[col + 1] : 0.f;
        acc[j][0] = bv0; acc[j][1] = bv1; acc[j][2] = bv0; acc[j][3] = bv1;
    }
#pragma unroll 4
    for (int ks = 0; ks < 16; ks++) {
        int k0 = ks * 8;
        uint32_t a0 = s_x[(mb + g) * 132 + k0 + tt];
        uint32_t a1 = s_x[(mb + g + 8) * 132 + k0 + tt];
        uint32_t a2 = s_x[(mb + g) * 132 + k0 + tt + 4];
        uint32_t a3 = s_x[(mb + g + 8) * 132 + k0 + tt + 4];
#pragma unroll
        for (int j = 0; j < 4; j++) {
            int n0 = wn * 32 + j * 8;
            uint32_t b0 = s_w[(k0 + tt) * 136 + n0 + g];
            uint32_t b1r = s_w[(k0 + tt + 4) * 136 + n0 + g];
            mma_tf32(acc[j], a0, a1, a2, a3, b0, b1r);
        }
    }
    __half* dstp = half ? g_Q16 : g_P16;
    int r_lo = n0t + mb + g, r_hi = r_lo + 8;
#pragma unroll
    for (int j = 0; j < 4; j++) {
        int col = nc * 128 + wn * 32 + j * 8 + 2 * tt;
        if (r_lo < N_NODES)
            *(uint32_t*)&dstp[(size_t)r_lo * HID + col] = f22h2u(acc[j][0], acc[j][1]);
        if (r_hi < N_NODES)
            *(uint32_t*)&dstp[(size_t)r_hi * HID + col] = f22h2u(acc[j][2], acc[j][3]);
    }
}

// ---------------- k_fused: 256 thr, 8 warps (4 wm x 2 wn), m32 x n64 ----------------
// SMEM bytes: [0,512) src | [512,1024) dst | [1024,2560) w20 |
//             [2560,35328) X/h (128 rows x 64 u32 words, XOR swizzle) |
//             [35328,133632) Wve [384][64] | [133632,231936) W23 [128][192]
#define SM_SRC  0
#define SM_DST  512
#define SM_W20  1024
#define SM_X    2560
#define SM_WVE  35328
#define SM_W23  133632
#define SMEM_F  231936

__global__ void __launch_bounds__(256, 1) k_fused(
    const float* __restrict__ ve1, const float* __restrict__ ve2,
    const int*   __restrict__ src, const int* __restrict__ dst,
    const float* __restrict__ W1,  const float* __restrict__ b3,
    float* __restrict__ out)
{
    extern __shared__ __align__(16) char smem[];
    int*      s_src  = (int*)(smem + SM_SRC);
    int*      s_dst  = (int*)(smem + SM_DST);
    float*    s_w20  = (float*)(smem + SM_W20);
    uint32_t* s_x    = (uint32_t*)(smem + SM_X);       // X, then h per chunk
    uint32_t* s_wve  = (uint32_t*)(smem + SM_WVE);
    uint32_t* s_w23  = (uint32_t*)(smem + SM_W23);
    float*    s_gp   = (float*)(smem + SM_X);          // overlay (h dead)
    float*    s_gate = (float*)(smem + SM_X + 4096);   // overlay (h dead)

    int t = threadIdx.x;
    int warp = t >> 5, lane = t & 31;
    int wm = warp >> 1, wn = warp & 1;      // 4 row-groups x 2 col-groups
    int g = lane >> 2, tt = lane & 3;
    uint32_t gsw = (uint32_t)g << 2;

    // ---- stage weights (once) ----
    for (int i = t; i < 384 * 64; i += 256) {        // Wve[n][k] = W1[256+k][n]
        int n = i >> 6, w = i & 63;
        int k = 2 * w;
        s_wve[(n << 6) + (w ^ ((n & 7) << 2))] =
            f22h2u(W1[(size_t)(256 + k) * HID + n], W1[(size_t)(257 + k) * HID + n]);
    }
    for (int i = t; i < 128 * 192; i += 256) {       // W23s[n][k] = g_W23[k][n]
        int n = i / 192, w = i - n * 192;
        int k = 2 * w;
        s_w23[n * 192 + (w ^ ((n & 7) << 2))] =
            f22h2u(g_W23[(size_t)k * DOUT + n], g_W23[(size_t)(k + 1) * DOUT + n]);
    }
    for (int i = t; i < HID; i += 256) s_w20[i] = g_w20[i];
    float b20 = g_b20;

    for (int tile = blockIdx.x; tile < NT; tile += gridDim.x) {
        int e0 = tile * TME;
        __syncthreads();   // prev tile epilogue done (s_gate reads) before X overwrite

        // ---- stage indices + X (fp32 -> fp16), coalesced 16-lanes-per-row ----
        if (t < 128) s_src[t] = src[e0 + t];
        else s_dst[t - 128] = dst[e0 + t - 128];
#pragma unroll
        for (int p = 0; p < 8; p++) {
            int xr = p * 16 + (t >> 4);
            int i  = t & 15;
            uint32_t rs = (uint32_t)xr << 6;
            uint32_t sw = (uint32_t)(xr & 7) << 2;
            float4 v1 = __ldg((const float4*)(ve1 + (size_t)(e0 + xr) * 64) + i);
            *(uint2*)&s_x[rs + (((uint32_t)(2 * i)) ^ sw)] =
                make_uint2(f22h2u(v1.x, v1.y), f22h2u(v1.z, v1.w));
            float4 v2 = __ldg((const float4*)(ve2 + (size_t)(e0 + xr) * 64) + i);
            *(uint2*)&s_x[rs + (((uint32_t)(32 + 2 * i)) ^ sw)] =
                make_uint2(f22h2u(v2.x, v2.y), f22h2u(v2.z, v2.w));
        }
        __syncthreads();

        // ---- load X A-fragments into registers (once per tile) ----
        uint32_t areg[2][8][4];
#pragma unroll
        for (int mf = 0; mf < 2; mf++) {
            int ra = wm * 32 + mf * 16 + g, rb = ra + 8;
#pragma unroll
            for (int ks = 0; ks < 8; ks++) {
                uint32_t wa = (uint32_t)(8 * ks + tt), wb = wa + 4;
                areg[mf][ks][0] = s_x[(ra << 6) + (wa ^ gsw)];
                areg[mf][ks][1] = s_x[(rb << 6) + (wa ^ gsw)];
                areg[mf][ks][2] = s_x[(ra << 6) + (wb ^ gsw)];
                areg[mf][ks][3] = s_x[(rb << 6) + (wb ^ gsw)];
            }
        }
        __syncthreads();   // all X reads complete before h overwrites region

        float acc2[2][8][4];
#pragma unroll
        for (int mf = 0; mf < 2; mf++)
#pragma unroll
            for (int j = 0; j < 8; j++)
#pragma unroll
                for (int i = 0; i < 4; i++) acc2[mf][j][i] = 0.f;
        float gacc[4] = {0.f, 0.f, 0.f, 0.f};

#pragma unroll 1
        for (int c = 0; c < 3; c++) {
            // ---- GEMM1 chunk: A from regs, B from s_wve ----
            float acc1[2][8][4];
#pragma unroll
            for (int mf = 0; mf < 2; mf++)
#pragma unroll
                for (int j = 0; j < 8; j++)
#pragma unroll
                    for (int i = 0; i < 4; i++) acc1[mf][j][i] = 0.f;
#pragma unroll
            for (int ks = 0; ks < 8; ks++) {
                uint32_t wa = (uint32_t)(8 * ks + tt), wb = wa + 4;
#pragma unroll
                for (int j = 0; j < 8; j++) {
                    int n = 128 * c + wn * 64 + j * 8 + g;
                    uint32_t b0 = s_wve[(n << 6) + (wa ^ gsw)];
                    uint32_t b1 = s_wve[(n << 6) + (wb ^ gsw)];
                    mma_f16(acc1[0][j], areg[0][ks][0], areg[0][ks][1],
                            areg[0][ks][2], areg[0][ks][3], b0, b1);
                    mma_f16(acc1[1][j], areg[1][ks][0], areg[1][ks][1],
                            areg[1][ks][2], areg[1][ks][3], b0, b1);
                }
            }
            // ---- epilogue: + P[src] + Q[dst], relu, gate partial, h -> smem ----
#pragma unroll
            for (int mf = 0; mf < 2; mf++) {
                int ra = wm * 32 + mf * 16 + g, rb = ra + 8;
                const __half* Pa = g_P16 + (size_t)s_src[ra] * HID + 128 * c;
                const __half* Qa = g_Q16 + (size_t)s_dst[ra] * HID + 128 * c;
                const __half* Pb = g_P16 + (size_t)s_src[rb] * HID + 128 * c;
                const __half* Qb = g_Q16 + (size_t)s_dst[rb] * HID + 128 * c;
#pragma unroll
                for (int j = 0; j < 8; j++) {
                    int col = wn * 64 + j * 8 + 2 * tt;
                    float2 pa = u2f2(__ldg((const uint32_t*)(Pa + col)));
                    float2 qa = u2f2(__ldg((const uint32_t*)(Qa + col)));
                    float2 pb = u2f2(__ldg((const uint32_t*)(Pb + col)));
                    float2 qb = u2f2(__ldg((const uint32_t*)(Qb + col)));
                    float h0 = fmaxf(acc1[mf][j][0] + pa.x + qa.x, 0.f);
                    float h1 = fmaxf(acc1[mf][j][1] + pa.y + qa.y, 0.f);
                    float h2 = fmaxf(acc1[mf][j][2] + pb.x + qb.x, 0.f);
                    float h3 = fmaxf(acc1[mf][j][3] + pb.y + qb.y, 0.f);
                    float2 wv = *(const float2*)&s_w20[128 * c + col];
                    gacc[2 * mf]     = fmaf(h0, wv.x, fmaf(h1, wv.y, gacc[2 * mf]));
                    gacc[2 * mf + 1] = fmaf(h2, wv.x, fmaf(h3, wv.y, gacc[2 * mf + 1]));
                    uint32_t wcl = (uint32_t)(wn * 32 + j * 4 + tt);
                    s_x[(ra << 6) + (wcl ^ gsw)] = f22h2u(h0, h1);
                    s_x[(rb << 6) + (wcl ^ gsw)] = f22h2u(h2, h3);
                }
            }
            WM_BAR(wm);   // h chunk visible within 64-thread wm pair

            // ---- GEMM2: acc2 += h_chunk @ W23[k-chunk c] ----
#pragma unroll
            for (int ks = 0; ks < 8; ks++) {
                uint32_t wa = (uint32_t)(8 * ks + tt), wb = wa + 4;
                uint32_t a[2][4];
#pragma unroll
                for (int mf = 0; mf < 2; mf++) {
                    int ra = wm * 32 + mf * 16 + g, rb = ra + 8;
                    a[mf][0] = s_x[(ra << 6) + (wa ^ gsw)];
                    a[mf][1] = s_x[(rb << 6) + (wa ^ gsw)];
                    a[mf][2] = s_x[(ra << 6) + (wb ^ gsw)];
                    a[mf][3] = s_x[(rb << 6) + (wb ^ gsw)];
                }
#pragma unroll
                for (int j = 0; j < 8; j++) {
                    int n = wn * 64 + j * 8 + g;
                    uint32_t w0 = (uint32_t)(64 * c + 8 * ks + tt);
                    uint32_t b0 = s_w23[n * 192 + (w0 ^ gsw)];
                    uint32_t b1 = s_w23[n * 192 + ((w0 + 4) ^ gsw)];
                    mma_f16(acc2[0][j], a[0][0], a[0][1], a[0][2], a[0][3], b0, b1);
                    mma_f16(acc2[1][j], a[1][0], a[1][1], a[1][2], a[1][3], b0, b1);
                }
            }
            WM_BAR(wm);   // h reads done before next chunk's h writes
        }

        // ---- gate: per-row partial reduce (overlay region; h now dead) ----
        __syncthreads();
#pragma unroll
        for (int mf = 0; mf < 2; mf++) {
            int ra = wm * 32 + mf * 16 + g;
            s_gp[ra * 8 + wn * 4 + tt]       = gacc[2 * mf];
            s_gp[(ra + 8) * 8 + wn * 4 + tt] = gacc[2 * mf + 1];
        }
        __syncthreads();
        if (t < 128) {
            float s = 0.f;
#pragma unroll
            for (int i = 0; i < 8; i++) s += s_gp[t * 8 + i];
            s_gate[t] = 1.f / (1.f + expf(-(s + b20)));
        }
        __syncthreads();

        // ---- output epilogue ----
#pragma unroll
        for (int mf = 0; mf < 2; mf++) {
            int ra = wm * 32 + mf * 16 + g, rb = ra + 8;
            float kl = s_gate[ra], kh = s_gate[rb];
#pragma unroll
            for (int j = 0; j < 8; j++) {
                int col = wn * 64 + j * 8 + 2 * tt;
                float2 cc = __ldg((const float2*)&g_c0[col]);
                float2 bb = __ldg((const float2*)&b3[col]);
                float2 o0, o1;
                o0.x = fmaf(kl, acc2[mf][j][0] + cc.x, bb.x);
                o0.y = fmaf(kl, acc2[mf][j][1] + cc.y, bb.y);
                o1.x = fmaf(kh, acc2[mf][j][2] + cc.x, bb.x);
                o1.y = fmaf(kh, acc2[mf][j][3] + cc.y, bb.y);
                *(float2*)&out[(size_t)(e0 + ra) * DOUT + col] = o0;
                *(float2*)&out[(size_t)(e0 + rb) * DOUT + col] = o1;
            }
        }
    }
}

// ---------------- launch ----------------
extern "C" void kernel_launch(void* const* d_in, const int* in_sizes, int n_in,
                              void* d_out, int out_size) {
    const float* vc  = (const float*)d_in[0];
    const float* ve1 = (const float*)d_in[1];
    const float* ve2 = (const float*)d_in[2];
    const int*   src = (const int*)  d_in[3];
    const int*   dst = (const int*)  d_in[4];
    const float* W1  = (const float*)d_in[5];
    const float* b1  = (const float*)d_in[6];
    const float* W2  = (const float*)d_in[7];
    const float* b2  = (const float*)d_in[8];
    const float* W3  = (const float*)d_in[9];
    const float* b3  = (const float*)d_in[10];
    float* out = (float*)d_out;

    const int smem_pq = (128 * 136 + 32 * 132) * 4;
    cudaFuncSetAttribute(k_pq,    cudaFuncAttributeMaxDynamicSharedMemorySize, smem_pq);
    cudaFuncSetAttribute(k_fused, cudaFuncAttributeMaxDynamicSharedMemorySize, SMEM_F);

    k_w23 <<<HID, 128>>>(W2, W3);
    k_misc<<<1, 512>>>(W2, b2, W3);
    k_pq  <<<dim3(6, (N_NODES + PQ_TM - 1) / PQ_TM), 256, smem_pq>>>(vc, W1, b1);
    k_fused<<<148, 256, SMEM_F>>>(ve1, ve2, src, dst, W1, b3, out);
}

// round 12
// speedup vs baseline: 1.5613x; 1.5613x over previous
#include <cuda_runtime.h>
#include <cuda_fp16.h>
#include <math.h>
#include <stdint.h>

#define N_NODES 50000
#define N_EDGES 800000
#define HID     384
#define DOUT    128
#define TME     128                 // edges per tile
#define NT      (N_EDGES / TME)     // 6250

// ---------------- device scratch ----------------
__device__ __half g_P16[(size_t)N_NODES * HID];   // vc @ W1[0:128]        (fp16)
__device__ __half g_Q16[(size_t)N_NODES * HID];   // vc @ W1[128:256] + b1 (fp16)
__device__ float  g_W23[HID * DOUT];              // W2[:,1:] @ W3
__device__ float  g_w20[HID];                     // W2[:,0]
__device__ float  g_c0[DOUT];                     // b2[1:] @ W3
__device__ float  g_b20;                          // b2[0]

// ---------------- helpers ----------------
__device__ __forceinline__ uint32_t f2tf(float f) {
    uint32_t u; asm("cvt.rna.tf32.f32 %0, %1;" : "=r"(u) : "f"(f)); return u;
}
__device__ __forceinline__ void mma_tf32(float c[4],
        uint32_t a0, uint32_t a1, uint32_t a2, uint32_t a3,
        uint32_t b0, uint32_t b1) {
    asm volatile("mma.sync.aligned.m16n8k8.row.col.f32.tf32.tf32.f32 "
        "{%0,%1,%2,%3}, {%4,%5,%6,%7}, {%8,%9}, {%0,%1,%2,%3};"
        : "+f"(c[0]), "+f"(c[1]), "+f"(c[2]), "+f"(c[3])
        : "r"(a0), "r"(a1), "r"(a2), "r"(a3), "r"(b0), "r"(b1));
}
__device__ __forceinline__ void mma_f16(float c[4],
        uint32_t a0, uint32_t a1, uint32_t a2, uint32_t a3,
        uint32_t b0, uint32_t b1) {
    asm volatile("mma.sync.aligned.m16n8k16.row.col.f32.f16.f16.f32 "
        "{%0,%1,%2,%3}, {%4,%5,%6,%7}, {%8,%9}, {%0,%1,%2,%3};"
        : "+f"(c[0]), "+f"(c[1]), "+f"(c[2]), "+f"(c[3])
        : "r"(a0), "r"(a1), "r"(a2), "r"(a3), "r"(b0), "r"(b1));
}
__device__ __forceinline__ void ldsm_x4(uint32_t r[4], uint32_t addr) {
    asm volatile("ldmatrix.sync.aligned.m8n8.x4.shared.b16 {%0,%1,%2,%3}, [%4];"
        : "=r"(r[0]), "=r"(r[1]), "=r"(r[2]), "=r"(r[3]) : "r"(addr));
}
__device__ __forceinline__ uint32_t f22h2u(float a, float b) {
    __half2 h = __floats2half2_rn(a, b);
    return *reinterpret_cast<uint32_t*>(&h);
}
__device__ __forceinline__ float2 u2f2(uint32_t u) {
    __half2 h = *reinterpret_cast<__half2*>(&u);
    return __half22float2(h);
}
__device__ __forceinline__ uint32_t smem_u32(const void* p) {
    uint32_t a;
    asm("{ .reg .u64 t; cvta.to.shared.u64 t, %1; cvt.u32.u64 %0, t; }" : "=r"(a) : "l"(p));
    return a;
}

// ---------------- tiny precompute kernels ----------------
__global__ void k_w23(const float* __restrict__ W2, const float* __restrict__ W3) {
    __shared__ float s[512];
    int k = blockIdx.x, t = threadIdx.x;
    for (int j = t; j < 512; j += 128) s[j] = W2[k * 513 + 1 + j];
    __syncthreads();
    float acc = 0.f;
#pragma unroll 8
    for (int j = 0; j < 512; j++) acc = fmaf(s[j], W3[j * DOUT + t], acc);
    g_W23[k * DOUT + t] = acc;
}
__global__ void k_misc(const float* __restrict__ W2, const float* __restrict__ b2,
                       const float* __restrict__ W3) {
    int t = threadIdx.x;
    if (t < HID) g_w20[t] = W2[t * 513];
    if (t < DOUT) {
        float acc = 0.f;
        for (int j = 0; j < 512; j++) acc = fmaf(b2[1 + j], W3[j * DOUT + t], acc);
        g_c0[t] = acc;
    }
    if (t == 0) g_b20 = b2[0];
}

// ---------------- k_pq (proven) ----------------
#define PQ_TM 32
__global__ void __launch_bounds__(256) k_pq(const float* __restrict__ vc,
                                            const float* __restrict__ W1,
                                            const float* __restrict__ b1) {
    extern __shared__ uint32_t smu[];
    uint32_t* s_w = smu;
    uint32_t* s_x = smu + 128 * 136;
    int t = threadIdx.x;
    int chunk = blockIdx.x;
    int half = chunk / 3, nc = chunk - half * 3;
    int n0t = blockIdx.y * PQ_TM;

    for (int i = t; i < 128 * 128; i += 256) {
        int k = i >> 7, n = i & 127;
        s_w[k * 136 + n] = f2tf(W1[(size_t)(half * 128 + k) * HID + nc * 128 + n]);
    }
    for (int i = t; i < PQ_TM * 128; i += 256) {
        int r = i >> 7, k = i & 127;
        int node = n0t + r; if (node >= N_NODES) node = N_NODES - 1;
        s_x[r * 132 + k] = f2tf(vc[(size_t)node * 128 + k]);
    }
    __syncthreads();
    int warp = t >> 5, lane = t & 31;
    int wm = warp >> 2, wn = warp & 3;
    int g = lane >> 2, tt = lane & 3;
    int mb = wm * 16;
    float acc[4][4];
#pragma unroll
    for (int j = 0; j < 4; j++) {
        int col = nc * 128 + wn * 32 + j * 8 + 2 * tt;
        float bv0 = half ? b1[col] : 0.f;
        float bv1 = half ? b1[col + 1] : 0.f;
        acc[j][0] = bv0; acc[j][1] = bv1; acc[j][2] = bv0; acc[j][3] = bv1;
    }
#pragma unroll 4
    for (int ks = 0; ks < 16; ks++) {
        int k0 = ks * 8;
        uint32_t a0 = s_x[(mb + g) * 132 + k0 + tt];
        uint32_t a1 = s_x[(mb + g + 8) * 132 + k0 + tt];
        uint32_t a2 = s_x[(mb + g) * 132 + k0 + tt + 4];
        uint32_t a3 = s_x[(mb + g + 8) * 132 + k0 + tt + 4];
#pragma unroll
        for (int j = 0; j < 4; j++) {
            int n0 = wn * 32 + j * 8;
            uint32_t b0 = s_w[(k0 + tt) * 136 + n0 + g];
            uint32_t b1r = s_w[(k0 + tt + 4) * 136 + n0 + g];
            mma_tf32(acc[j], a0, a1, a2, a3, b0, b1r);
        }
    }
    __half* dstp = half ? g_Q16 : g_P16;
    int r_lo = n0t + mb + g, r_hi = r_lo + 8;
#pragma unroll
    for (int j = 0; j < 4; j++) {
        int col = nc * 128 + wn * 32 + j * 8 + 2 * tt;
        if (r_lo < N_NODES)
            *(uint32_t*)&dstp[(size_t)r_lo * HID + col] = f22h2u(acc[j][0], acc[j][1]);
        if (r_hi < N_NODES)
            *(uint32_t*)&dstp[(size_t)r_hi * HID + col] = f22h2u(acc[j][2], acc[j][3]);
    }
}

// ---------------- k_fused: 8 warps x m16 rows; h lives in registers ----------------
// SMEM: [0,512) src | [512,1024) dst | [1024,2560) w20 |
//       [2560,35328) X (128 x 64 words, XOR swz) | [35328,133632) Wve [384][64] |
//       [133632,231936) W23 [128][192]
#define SM_SRC  0
#define SM_DST  512
#define SM_W20  1024
#define SM_X    2560
#define SM_WVE  35328
#define SM_W23  133632
#define SMEM_F  231936

__global__ void __launch_bounds__(256, 1) k_fused(
    const float* __restrict__ ve1, const float* __restrict__ ve2,
    const int*   __restrict__ src, const int* __restrict__ dst,
    const float* __restrict__ W1,  const float* __restrict__ b3,
    float* __restrict__ out)
{
    extern __shared__ __align__(16) char smem[];
    int*      s_src = (int*)(smem + SM_SRC);
    int*      s_dst = (int*)(smem + SM_DST);
    float*    s_w20 = (float*)(smem + SM_W20);
    uint32_t* s_x   = (uint32_t*)(smem + SM_X);
    uint32_t* s_wve = (uint32_t*)(smem + SM_WVE);
    uint32_t* s_w23 = (uint32_t*)(smem + SM_W23);

    int t = threadIdx.x;
    int warp = t >> 5, lane = t & 31;
    int wm = warp;                       // warp owns rows [wm*16, wm*16+16)
    int g = lane >> 2, tt = lane & 3;

    // ---- stage weights (once) ----
    for (int i = t; i < 384 * 64; i += 256) {        // Wve[n][k] = W1[256+k][n]
        int n = i >> 6, w = i & 63;
        int k = 2 * w;
        s_wve[(n << 6) + (w ^ ((n & 7) << 2))] =
            f22h2u(W1[(size_t)(256 + k) * HID + n], W1[(size_t)(257 + k) * HID + n]);
    }
    for (int i = t; i < 128 * 192; i += 256) {       // W23s[n][k] = g_W23[k][n]
        int n = i / 192, w = i - n * 192;
        int k = 2 * w;
        s_w23[n * 192 + (w ^ ((n & 7) << 2))] =
            f22h2u(g_W23[(size_t)k * DOUT + n], g_W23[(size_t)(k + 1) * DOUT + n]);
    }
    for (int i = t; i < HID; i += 256) s_w20[i] = g_w20[i];
    float b20 = g_b20;

    // ---- ldmatrix lane constants ----
    // A (X / m16k16): m0=(mlo,klo) m1=(mhi,klo) m2=(mlo,khi) m3=(mhi,khi)
    int arow_off = ((lane >> 3) & 1) * 8 + (lane & 7);
    uint32_t wsel_a = (uint32_t)(((lane >> 4) & 1) * 4);
    // B (n16k16): m0=(nlo,klo) m1=(nlo,khi) m2=(nhi,klo) m3=(nhi,khi)
    int nrow_off = ((lane >> 4) & 1) * 8 + (lane & 7);
    uint32_t wsel_b = (uint32_t)(((lane >> 3) & 1) * 4);
    uint32_t slxB = (uint32_t)(nrow_off & 7) << 2;

    uint32_t sxu  = smem_u32(smem + SM_X);
    uint32_t wveu = smem_u32(smem + SM_WVE);
    uint32_t w23u = smem_u32(smem + SM_W23);
    // per-lane fixed parts
    int ar = wm * 16 + arow_off;
    uint32_t aswz = (uint32_t)(ar & 7) << 2;
    uint32_t a_base = sxu + ((uint32_t)ar << 8);            // row * 64 words * 4B
    uint32_t wve_lane = wveu + ((uint32_t)nrow_off << 8);   // + n*256B
    uint32_t w23_lane = w23u + (uint32_t)nrow_off * 768u;   // + n*192 words*4B

    int ra = wm * 16 + g, rb = ra + 8;

    for (int tile = blockIdx.x; tile < NT; tile += gridDim.x) {
        int e0 = tile * TME;
        __syncthreads();    // prior tile done with s_x / indices

        // ---- stage indices + X (fp32 -> fp16) ----
        if (t < 128) s_src[t] = src[e0 + t];
        else s_dst[t - 128] = dst[e0 + t - 128];
#pragma unroll
        for (int p = 0; p < 8; p++) {
            int xr = p * 16 + (t >> 4);
            int i  = t & 15;
            uint32_t rs = (uint32_t)xr << 6;
            uint32_t sw = (uint32_t)(xr & 7) << 2;
            float4 v1 = __ldg((const float4*)(ve1 + (size_t)(e0 + xr) * 64) + i);
            *(uint2*)&s_x[rs + (((uint32_t)(2 * i)) ^ sw)] =
                make_uint2(f22h2u(v1.x, v1.y), f22h2u(v1.z, v1.w));
            float4 v2 = __ldg((const float4*)(ve2 + (size_t)(e0 + xr) * 64) + i);
            *(uint2*)&s_x[rs + (((uint32_t)(32 + 2 * i)) ^ sw)] =
                make_uint2(f22h2u(v2.x, v2.y), f22h2u(v2.z, v2.w));
        }
        __syncthreads();

        // ---- A-fragments for X (once per tile) ----
        uint32_t areg[8][4];
#pragma unroll
        for (int ks = 0; ks < 8; ks++)
            ldsm_x4(areg[ks], a_base + 4u * (((uint32_t)(8 * ks) + wsel_a) ^ aswz));

        // ---- row pointers for P/Q gather ----
        const __half* Pa = g_P16 + (size_t)s_src[ra] * HID;
        const __half* Qa = g_Q16 + (size_t)s_dst[ra] * HID;
        const __half* Pb = g_P16 + (size_t)s_src[rb] * HID;
        const __half* Qb = g_Q16 + (size_t)s_dst[rb] * HID;

        float acc2[16][4];
#pragma unroll
        for (int j = 0; j < 16; j++)
#pragma unroll
            for (int i = 0; i < 4; i++) acc2[j][i] = 0.f;
        float ggl = 0.f, ggh = 0.f;

        // prefetch P/Q for chunk 0 (cols 2tt, 8+2tt)
        uint32_t pa0 = __ldg((const uint32_t*)(Pa + 2 * tt));
        uint32_t pa1 = __ldg((const uint32_t*)(Pa + 8 + 2 * tt));
        uint32_t qa0 = __ldg((const uint32_t*)(Qa + 2 * tt));
        uint32_t qa1 = __ldg((const uint32_t*)(Qa + 8 + 2 * tt));
        uint32_t pb0 = __ldg((const uint32_t*)(Pb + 2 * tt));
        uint32_t pb1 = __ldg((const uint32_t*)(Pb + 8 + 2 * tt));
        uint32_t qb0 = __ldg((const uint32_t*)(Qb + 2 * tt));
        uint32_t qb1 = __ldg((const uint32_t*)(Qb + 8 + 2 * tt));

#pragma unroll 1
        for (int j = 0; j < 24; j++) {
            // ---- GEMM1 chunk: h[:, 16j..16j+16) ----
            float A1[4] = {0.f, 0.f, 0.f, 0.f};   // n-lo (cols 16j+2tt)
            float B1[4] = {0.f, 0.f, 0.f, 0.f};   // n-hi (cols 16j+8+2tt)
            uint32_t wbase = wve_lane + ((uint32_t)j << 12);   // 16j rows * 256B
#pragma unroll
            for (int ks = 0; ks < 8; ks++) {
                uint32_t bw[4];
                ldsm_x4(bw, wbase + 4u * (((uint32_t)(8 * ks) + wsel_b) ^ slxB));
                mma_f16(A1, areg[ks][0], areg[ks][1], areg[ks][2], areg[ks][3], bw[0], bw[1]);
                mma_f16(B1, areg[ks][0], areg[ks][1], areg[ks][2], areg[ks][3], bw[2], bw[3]);
            }
            // ---- epilogue: +P+Q, relu, gate partial, pack to A-frag ----
            float2 fpa0 = u2f2(pa0), fqa0 = u2f2(qa0), fpa1 = u2f2(pa1), fqa1 = u2f2(qa1);
            float2 fpb0 = u2f2(pb0), fqb0 = u2f2(qb0), fpb1 = u2f2(pb1), fqb1 = u2f2(qb1);
            float h00 = fmaxf(A1[0] + fpa0.x + fqa0.x, 0.f);
            float h01 = fmaxf(A1[1] + fpa0.y + fqa0.y, 0.f);
            float h10 = fmaxf(A1[2] + fpb0.x + fqb0.x, 0.f);
            float h11 = fmaxf(A1[3] + fpb0.y + fqb0.y, 0.f);
            float h02 = fmaxf(B1[0] + fpa1.x + fqa1.x, 0.f);
            float h03 = fmaxf(B1[1] + fpa1.y + fqa1.y, 0.f);
            float h12 = fmaxf(B1[2] + fpb1.x + fqb1.x, 0.f);
            float h13 = fmaxf(B1[3] + fpb1.y + fqb1.y, 0.f);
            float2 wlo = *(const float2*)&s_w20[16 * j + 2 * tt];
            float2 whi = *(const float2*)&s_w20[16 * j + 8 + 2 * tt];
            ggl = fmaf(h00, wlo.x, fmaf(h01, wlo.y, fmaf(h02, whi.x, fmaf(h03, whi.y, ggl))));
            ggh = fmaf(h10, wlo.x, fmaf(h11, wlo.y, fmaf(h12, whi.x, fmaf(h13, whi.y, ggh))));
            uint32_t hf0 = f22h2u(h00, h01);
            uint32_t hf1 = f22h2u(h10, h11);
            uint32_t hf2 = f22h2u(h02, h03);
            uint32_t hf3 = f22h2u(h12, h13);
            // ---- prefetch P/Q for next chunk ----
            if (j < 23) {
                int c0 = 16 * (j + 1) + 2 * tt, c1 = c0 + 8;
                pa0 = __ldg((const uint32_t*)(Pa + c0));
                pa1 = __ldg((const uint32_t*)(Pa + c1));
                qa0 = __ldg((const uint32_t*)(Qa + c0));
                qa1 = __ldg((const uint32_t*)(Qa + c1));
                pb0 = __ldg((const uint32_t*)(Pb + c0));
                pb1 = __ldg((const uint32_t*)(Pb + c1));
                qb0 = __ldg((const uint32_t*)(Qb + c0));
                qb1 = __ldg((const uint32_t*)(Qb + c1));
            }
            // ---- GEMM2 partial: acc2 += h_chunk @ W23[k-chunk j] ----
            uint32_t w2base = w23_lane + 4u * (((uint32_t)(8 * j) + wsel_b) ^ slxB);
#pragma unroll
            for (int jj = 0; jj < 8; jj++) {
                uint32_t b2[4];
                ldsm_x4(b2, w2base + (uint32_t)jj * 12288u);   // 16 rows * 768B
                mma_f16(acc2[2 * jj],     hf0, hf1, hf2, hf3, b2[0], b2[1]);
                mma_f16(acc2[2 * jj + 1], hf0, hf1, hf2, hf3, b2[2], b2[3]);
            }
        }

        // ---- gate finalize (warp-local quad reduce) ----
        ggl += __shfl_xor_sync(0xffffffffu, ggl, 1);
        ggl += __shfl_xor_sync(0xffffffffu, ggl, 2);
        ggh += __shfl_xor_sync(0xffffffffu, ggh, 1);
        ggh += __shfl_xor_sync(0xffffffffu, ggh, 2);
        float gl = 1.f / (1.f + expf(-(ggl + b20)));
        float gh = 1.f / (1.f + expf(-(ggh + b20)));

        // ---- output epilogue ----
        float* outa = out + (size_t)(e0 + ra) * DOUT;
        float* outb = out + (size_t)(e0 + rb) * DOUT;
#pragma unroll
        for (int jj = 0; jj < 16; jj++) {
            int col = 8 * jj + 2 * tt;
            float2 cc = __ldg((const float2*)&g_c0[col]);
            float2 bb = __ldg((const float2*)&b3[col]);
            float2 o0, o1;
            o0.x = fmaf(gl, acc2[jj][0] + cc.x, bb.x);
            o0.y = fmaf(gl, acc2[jj][1] + cc.y, bb.y);
            o1.x = fmaf(gh, acc2[jj][2] + cc.x, bb.x);
            o1.y = fmaf(gh, acc2[jj][3] + cc.y, bb.y);
            *(float2*)(outa + col) = o0;
            *(float2*)(outb + col) = o1;
        }
    }
}

// ---------------- launch ----------------
extern "C" void kernel_launch(void* const* d_in, const int* in_sizes, int n_in,
                              void* d_out, int out_size) {
    const float* vc  = (const float*)d_in[0];
    const float* ve1 = (const float*)d_in[1];
    const float* ve2 = (const float*)d_in[2];
    const int*   src = (const int*)  d_in[3];
    const int*   dst = (const int*)  d_in[4];
    const float* W1  = (const float*)d_in[5];
    const float* b1  = (const float*)d_in[6];
    const float* W2  = (const float*)d_in[7];
    const float* b2  = (const float*)d_in[8];
    const float* W3  = (const float*)d_in[9];
    const float* b3  = (const float*)d_in[10];
    float* out = (float*)d_out;

    const int smem_pq = (128 * 136 + 32 * 132) * 4;
    cudaFuncSetAttribute(k_pq,    cudaFuncAttributeMaxDynamicSharedMemorySize, smem_pq);
    cudaFuncSetAttribute(k_fused, cudaFuncAttributeMaxDynamicSharedMemorySize, SMEM_F);

    k_w23 <<<HID, 128>>>(W2, W3);
    k_misc<<<1, 512>>>(W2, b2, W3);
    k_pq  <<<dim3(6, (N_NODES + PQ_TM - 1) / PQ_TM), 256, smem_pq>>>(vc, W1, b1);
    k_fused<<<148, 256, SMEM_F>>>(ve1, ve2, src, dst, W1, b3, out);
}

// round 13
// speedup vs baseline: 1.9365x; 1.2403x over previous
#include <cuda_runtime.h>
#include <cuda_fp16.h>
#include <math.h>
#include <stdint.h>

#define N_NODES 50000
#define N_EDGES 800000
#define HID     384
#define DOUT    128
#define TME     128                 // edges per tile
#define NT      (N_EDGES / TME)     // 6250
#define NTPQ    ((N_NODES + 127) / 128)   // 391 node tiles

// ---------------- device scratch ----------------
__device__ __half g_P16[(size_t)N_NODES * HID];   // vc @ W1[0:128]        (fp16)
__device__ __half g_Q16[(size_t)N_NODES * HID];   // vc @ W1[128:256] + b1 (fp16)
__device__ float  g_W23[HID * DOUT];              // W2[:,1:] @ W3
__device__ float  g_w20[HID];                     // W2[:,0]
__device__ float  g_c0[DOUT];                     // b2[1:] @ W3
__device__ float  g_b20;                          // b2[0]

// ---------------- helpers ----------------
__device__ __forceinline__ void mma_f16(float c[4],
        uint32_t a0, uint32_t a1, uint32_t a2, uint32_t a3,
        uint32_t b0, uint32_t b1) {
    asm volatile("mma.sync.aligned.m16n8k16.row.col.f32.f16.f16.f32 "
        "{%0,%1,%2,%3}, {%4,%5,%6,%7}, {%8,%9}, {%0,%1,%2,%3};"
        : "+f"(c[0]), "+f"(c[1]), "+f"(c[2]), "+f"(c[3])
        : "r"(a0), "r"(a1), "r"(a2), "r"(a3), "r"(b0), "r"(b1));
}
__device__ __forceinline__ void ldsm_x4(uint32_t r[4], uint32_t addr) {
    asm volatile("ldmatrix.sync.aligned.m8n8.x4.shared.b16 {%0,%1,%2,%3}, [%4];"
        : "=r"(r[0]), "=r"(r[1]), "=r"(r[2]), "=r"(r[3]) : "r"(addr));
}
__device__ __forceinline__ uint32_t f22h2u(float a, float b) {
    __half2 h = __floats2half2_rn(a, b);
    return *reinterpret_cast<uint32_t*>(&h);
}
__device__ __forceinline__ float2 u2f2(uint32_t u) {
    __half2 h = *reinterpret_cast<__half2*>(&u);
    return __half22float2(h);
}
__device__ __forceinline__ uint32_t smem_u32(const void* p) {
    uint32_t a;
    asm("{ .reg .u64 t; cvta.to.shared.u64 t, %1; cvt.u32.u64 %0, t; }" : "=r"(a) : "l"(p));
    return a;
}

// ---------------- tiny precompute kernels ----------------
__global__ void k_w23(const float* __restrict__ W2, const float* __restrict__ W3) {
    __shared__ float s[512];
    int k = blockIdx.x, t = threadIdx.x;
    for (int j = t; j < 512; j += 128) s[j] = W2[k * 513 + 1 + j];
    __syncthreads();
    float acc = 0.f;
#pragma unroll 8
    for (int j = 0; j < 512; j++) acc = fmaf(s[j], W3[j * DOUT + t], acc);
    g_W23[k * DOUT + t] = acc;
}
__global__ void k_misc(const float* __restrict__ W2, const float* __restrict__ b2,
                       const float* __restrict__ W3) {
    int t = threadIdx.x;
    if (t < HID) g_w20[t] = W2[t * 513];
    if (t < DOUT) {
        float acc = 0.f;
        for (int j = 0; j < 512; j++) acc = fmaf(b2[1 + j], W3[j * DOUT + t], acc);
        g_c0[t] = acc;
    }
    if (t == 0) g_b20 = b2[0];
}

// ---------------- k_pq2: node GEMM, persistent, fp16 mma ----------------
// SMEM: [0,32768) X (128 x 64 words, XOR swz) | [32768,+98304) Wp | [+98304) Wq
#define PQ_SMX  0
#define PQ_SMW  32768
#define PQ_SMEM (32768 + 2 * 98304)   // 229376

__global__ void __launch_bounds__(256, 1) k_pq2(const float* __restrict__ vc,
                                                const float* __restrict__ W1,
                                                const float* __restrict__ b1) {
    extern __shared__ __align__(16) char smem[];
    uint32_t* s_x = (uint32_t*)(smem + PQ_SMX);
    uint32_t* s_w = (uint32_t*)(smem + PQ_SMW);

    int t = threadIdx.x;
    int warp = t >> 5, lane = t & 31;
    int wm = warp;
    int g = lane >> 2, tt = lane & 3;

    // stage both W halves: W[half][n][k] = W1[half*128+k][n]
    for (int i = t; i < 2 * 384 * 64; i += 256) {
        int half = i / (384 * 64), r = i - half * 384 * 64;
        int n = r >> 6, w = r & 63;
        int k = 2 * w;
        s_w[half * 24576 + (n << 6) + (w ^ ((n & 7) << 2))] =
            f22h2u(W1[(size_t)(half * 128 + k) * HID + n],
                   W1[(size_t)(half * 128 + k + 1) * HID + n]);
    }

    // ldmatrix lane constants (same as k_fused)
    int arow_off = ((lane >> 3) & 1) * 8 + (lane & 7);
    uint32_t wsel_a = (uint32_t)(((lane >> 4) & 1) * 4);
    int nrow_off = ((lane >> 4) & 1) * 8 + (lane & 7);
    uint32_t wsel_b = (uint32_t)(((lane >> 3) & 1) * 4);
    uint32_t slxB = (uint32_t)(nrow_off & 7) << 2;

    uint32_t sxu = smem_u32(smem + PQ_SMX);
    uint32_t swu = smem_u32(smem + PQ_SMW);
    int ar = wm * 16 + arow_off;
    uint32_t aswz = (uint32_t)(ar & 7) << 2;
    uint32_t a_base = sxu + ((uint32_t)ar << 8);
    uint32_t w_lane = swu + ((uint32_t)nrow_off << 8);
    int ra_off = wm * 16 + g;
    __syncthreads();

    for (int tile = blockIdx.x; tile < NTPQ; tile += gridDim.x) {
        int n0 = tile * 128;
        __syncthreads();
        // stage X = vc rows (fp32 -> fp16)
#pragma unroll
        for (int p = 0; p < 8; p++) {
            int xr = p * 16 + (t >> 4);
            int i  = t & 15;
            int node = n0 + xr; if (node >= N_NODES) node = N_NODES - 1;
            uint32_t rs = (uint32_t)xr << 6;
            uint32_t sw = (uint32_t)(xr & 7) << 2;
            float4 v1 = __ldg((const float4*)(vc + (size_t)node * 128) + i);
            *(uint2*)&s_x[rs + (((uint32_t)(2 * i)) ^ sw)] =
                make_uint2(f22h2u(v1.x, v1.y), f22h2u(v1.z, v1.w));
            float4 v2 = __ldg((const float4*)(vc + (size_t)node * 128) + 16 + i);
            *(uint2*)&s_x[rs + (((uint32_t)(32 + 2 * i)) ^ sw)] =
                make_uint2(f22h2u(v2.x, v2.y), f22h2u(v2.z, v2.w));
        }
        __syncthreads();

        uint32_t areg[8][4];
#pragma unroll
        for (int ks = 0; ks < 8; ks++)
            ldsm_x4(areg[ks], a_base + 4u * (((uint32_t)(8 * ks) + wsel_a) ^ aswz));

        int ra = n0 + ra_off, rb = ra + 8;
#pragma unroll 1
        for (int half = 0; half < 2; half++) {
            __half* dstp = half ? g_Q16 : g_P16;
            uint32_t wl = w_lane + (uint32_t)half * 98304u;
#pragma unroll 1
            for (int j = 0; j < 24; j++) {
                float A1[4] = {0.f, 0.f, 0.f, 0.f};
                float B1[4] = {0.f, 0.f, 0.f, 0.f};
                uint32_t wbase = wl + ((uint32_t)j << 12);
#pragma unroll
                for (int ks = 0; ks < 8; ks++) {
                    uint32_t bw[4];
                    ldsm_x4(bw, wbase + 4u * (((uint32_t)(8 * ks) + wsel_b) ^ slxB));
                    mma_f16(A1, areg[ks][0], areg[ks][1], areg[ks][2], areg[ks][3], bw[0], bw[1]);
                    mma_f16(B1, areg[ks][0], areg[ks][1], areg[ks][2], areg[ks][3], bw[2], bw[3]);
                }
                float2 blo = make_float2(0.f, 0.f), bhi = make_float2(0.f, 0.f);
                if (half) {
                    blo = __ldg((const float2*)&b1[16 * j + 2 * tt]);
                    bhi = __ldg((const float2*)&b1[16 * j + 8 + 2 * tt]);
                }
                if (ra < N_NODES) {
                    *(uint32_t*)&dstp[(size_t)ra * HID + 16 * j + 2 * tt] =
                        f22h2u(A1[0] + blo.x, A1[1] + blo.y);
                    *(uint32_t*)&dstp[(size_t)ra * HID + 16 * j + 8 + 2 * tt] =
                        f22h2u(B1[0] + bhi.x, B1[1] + bhi.y);
                }
                if (rb < N_NODES) {
                    *(uint32_t*)&dstp[(size_t)rb * HID + 16 * j + 2 * tt] =
                        f22h2u(A1[2] + blo.x, A1[3] + blo.y);
                    *(uint32_t*)&dstp[(size_t)rb * HID + 16 * j + 8 + 2 * tt] =
                        f22h2u(B1[2] + bhi.x, B1[3] + bhi.y);
                }
            }
        }
    }
}

// ---------------- k_fused: 8 warps x m16; h in registers; pipelined ----------------
#define SM_SRC  0
#define SM_DST  512
#define SM_W20  1024
#define SM_X    2560
#define SM_WVE  35328
#define SM_W23  133632
#define SMEM_F  231936

__global__ void __launch_bounds__(256, 1) k_fused(
    const float* __restrict__ ve1, const float* __restrict__ ve2,
    const int*   __restrict__ src, const int* __restrict__ dst,
    const float* __restrict__ W1,  const float* __restrict__ b3,
    float* __restrict__ out)
{
    extern __shared__ __align__(16) char smem[];
    int*      s_src = (int*)(smem + SM_SRC);
    int*      s_dst = (int*)(smem + SM_DST);
    float*    s_w20 = (float*)(smem + SM_W20);
    uint32_t* s_x   = (uint32_t*)(smem + SM_X);
    uint32_t* s_wve = (uint32_t*)(smem + SM_WVE);
    uint32_t* s_w23 = (uint32_t*)(smem + SM_W23);

    int t = threadIdx.x;
    int warp = t >> 5, lane = t & 31;
    int wm = warp;
    int g = lane >> 2, tt = lane & 3;

    for (int i = t; i < 384 * 64; i += 256) {
        int n = i >> 6, w = i & 63;
        int k = 2 * w;
        s_wve[(n << 6) + (w ^ ((n & 7) << 2))] =
            f22h2u(W1[(size_t)(256 + k) * HID + n], W1[(size_t)(257 + k) * HID + n]);
    }
    for (int i = t; i < 128 * 192; i += 256) {
        int n = i / 192, w = i - n * 192;
        int k = 2 * w;
        s_w23[n * 192 + (w ^ ((n & 7) << 2))] =
            f22h2u(g_W23[(size_t)k * DOUT + n], g_W23[(size_t)(k + 1) * DOUT + n]);
    }
    for (int i = t; i < HID; i += 256) s_w20[i] = g_w20[i];
    float b20 = g_b20;

    int arow_off = ((lane >> 3) & 1) * 8 + (lane & 7);
    uint32_t wsel_a = (uint32_t)(((lane >> 4) & 1) * 4);
    int nrow_off = ((lane >> 4) & 1) * 8 + (lane & 7);
    uint32_t wsel_b = (uint32_t)(((lane >> 3) & 1) * 4);
    uint32_t slxB = (uint32_t)(nrow_off & 7) << 2;

    uint32_t sxu  = smem_u32(smem + SM_X);
    uint32_t wveu = smem_u32(smem + SM_WVE);
    uint32_t w23u = smem_u32(smem + SM_W23);
    int ar = wm * 16 + arow_off;
    uint32_t aswz = (uint32_t)(ar & 7) << 2;
    uint32_t a_base = sxu + ((uint32_t)ar << 8);
    uint32_t wve_lane = wveu + ((uint32_t)nrow_off << 8);
    uint32_t w23_lane = w23u + (uint32_t)nrow_off * 768u;

    int ra = wm * 16 + g, rb = ra + 8;

    for (int tile = blockIdx.x; tile < NT; tile += gridDim.x) {
        int e0 = tile * TME;
        __syncthreads();

        if (t < 128) s_src[t] = src[e0 + t];
        else s_dst[t - 128] = dst[e0 + t - 128];
#pragma unroll
        for (int p = 0; p < 8; p++) {
            int xr = p * 16 + (t >> 4);
            int i  = t & 15;
            uint32_t rs = (uint32_t)xr << 6;
            uint32_t sw = (uint32_t)(xr & 7) << 2;
            float4 v1 = __ldg((const float4*)(ve1 + (size_t)(e0 + xr) * 64) + i);
            *(uint2*)&s_x[rs + (((uint32_t)(2 * i)) ^ sw)] =
                make_uint2(f22h2u(v1.x, v1.y), f22h2u(v1.z, v1.w));
            float4 v2 = __ldg((const float4*)(ve2 + (size_t)(e0 + xr) * 64) + i);
            *(uint2*)&s_x[rs + (((uint32_t)(32 + 2 * i)) ^ sw)] =
                make_uint2(f22h2u(v2.x, v2.y), f22h2u(v2.z, v2.w));
        }
        __syncthreads();

        uint32_t areg[8][4];
#pragma unroll
        for (int ks = 0; ks < 8; ks++)
            ldsm_x4(areg[ks], a_base + 4u * (((uint32_t)(8 * ks) + wsel_a) ^ aswz));

        const __half* Pa = g_P16 + (size_t)s_src[ra] * HID;
        const __half* Qa = g_Q16 + (size_t)s_dst[ra] * HID;
        const __half* Pb = g_P16 + (size_t)s_src[rb] * HID;
        const __half* Qb = g_Q16 + (size_t)s_dst[rb] * HID;

        float acc2[16][4];
#pragma unroll
        for (int j = 0; j < 16; j++)
#pragma unroll
            for (int i = 0; i < 4; i++) acc2[j][i] = 0.f;
        float ggl = 0.f, ggh = 0.f;

        // pq regs for current chunk
        uint32_t pa0 = __ldg((const uint32_t*)(Pa + 2 * tt));
        uint32_t pa1 = __ldg((const uint32_t*)(Pa + 8 + 2 * tt));
        uint32_t qa0 = __ldg((const uint32_t*)(Qa + 2 * tt));
        uint32_t qa1 = __ldg((const uint32_t*)(Qa + 8 + 2 * tt));
        uint32_t pb0 = __ldg((const uint32_t*)(Pb + 2 * tt));
        uint32_t pb1 = __ldg((const uint32_t*)(Pb + 8 + 2 * tt));
        uint32_t qb0 = __ldg((const uint32_t*)(Qb + 2 * tt));
        uint32_t qb1 = __ldg((const uint32_t*)(Qb + 8 + 2 * tt));

        uint32_t hf0, hf1, hf2, hf3;
        // ---- peel: GEMM1 + epilogue for chunk 0 ----
        {
            float A1[4] = {0.f, 0.f, 0.f, 0.f};
            float B1[4] = {0.f, 0.f, 0.f, 0.f};
#pragma unroll
            for (int ks = 0; ks < 8; ks++) {
                uint32_t bw[4];
                ldsm_x4(bw, wve_lane + 4u * (((uint32_t)(8 * ks) + wsel_b) ^ slxB));
                mma_f16(A1, areg[ks][0], areg[ks][1], areg[ks][2], areg[ks][3], bw[0], bw[1]);
                mma_f16(B1, areg[ks][0], areg[ks][1], areg[ks][2], areg[ks][3], bw[2], bw[3]);
            }
            float2 fpa0 = u2f2(pa0), fqa0 = u2f2(qa0), fpa1 = u2f2(pa1), fqa1 = u2f2(qa1);
            float2 fpb0 = u2f2(pb0), fqb0 = u2f2(qb0), fpb1 = u2f2(pb1), fqb1 = u2f2(qb1);
            float h00 = fmaxf(A1[0] + fpa0.x + fqa0.x, 0.f);
            float h01 = fmaxf(A1[1] + fpa0.y + fqa0.y, 0.f);
            float h10 = fmaxf(A1[2] + fpb0.x + fqb0.x, 0.f);
            float h11 = fmaxf(A1[3] + fpb0.y + fqb0.y, 0.f);
            float h02 = fmaxf(B1[0] + fpa1.x + fqa1.x, 0.f);
            float h03 = fmaxf(B1[1] + fpa1.y + fqa1.y, 0.f);
            float h12 = fmaxf(B1[2] + fpb1.x + fqb1.x, 0.f);
            float h13 = fmaxf(B1[3] + fpb1.y + fqb1.y, 0.f);
            float2 wlo = *(const float2*)&s_w20[2 * tt];
            float2 whi = *(const float2*)&s_w20[8 + 2 * tt];
            ggl = fmaf(h00, wlo.x, fmaf(h01, wlo.y, fmaf(h02, whi.x, fmaf(h03, whi.y, ggl))));
            ggh = fmaf(h10, wlo.x, fmaf(h11, wlo.y, fmaf(h12, whi.x, fmaf(h13, whi.y, ggh))));
            hf0 = f22h2u(h00, h01); hf1 = f22h2u(h10, h11);
            hf2 = f22h2u(h02, h03); hf3 = f22h2u(h12, h13);
            // prefetch pq for chunk 1
            pa0 = __ldg((const uint32_t*)(Pa + 16 + 2 * tt));
            pa1 = __ldg((const uint32_t*)(Pa + 24 + 2 * tt));
            qa0 = __ldg((const uint32_t*)(Qa + 16 + 2 * tt));
            qa1 = __ldg((const uint32_t*)(Qa + 24 + 2 * tt));
            pb0 = __ldg((const uint32_t*)(Pb + 16 + 2 * tt));
            pb1 = __ldg((const uint32_t*)(Pb + 24 + 2 * tt));
            qb0 = __ldg((const uint32_t*)(Qb + 16 + 2 * tt));
            qb1 = __ldg((const uint32_t*)(Qb + 24 + 2 * tt));
        }

        // ---- fused pipeline: GEMM2(j) interleaved with GEMM1(j+1) ----
#pragma unroll 1
        for (int j = 0; j < 24; j++) {
            bool more = (j < 23);
            float A1[4] = {0.f, 0.f, 0.f, 0.f};
            float B1[4] = {0.f, 0.f, 0.f, 0.f};
            uint32_t wbase = wve_lane + ((uint32_t)(j + 1) << 12);
            uint32_t w2base = w23_lane + 4u * (((uint32_t)(8 * j) + wsel_b) ^ slxB);
#pragma unroll
            for (int ks = 0; ks < 8; ks++) {
                uint32_t b2[4];
                ldsm_x4(b2, w2base + (uint32_t)ks * 12288u);
                mma_f16(acc2[2 * ks],     hf0, hf1, hf2, hf3, b2[0], b2[1]);
                mma_f16(acc2[2 * ks + 1], hf0, hf1, hf2, hf3, b2[2], b2[3]);
                if (more) {
                    uint32_t bw[4];
                    ldsm_x4(bw, wbase + 4u * (((uint32_t)(8 * ks) + wsel_b) ^ slxB));
                    mma_f16(A1, areg[ks][0], areg[ks][1], areg[ks][2], areg[ks][3], bw[0], bw[1]);
                    mma_f16(B1, areg[ks][0], areg[ks][1], areg[ks][2], areg[ks][3], bw[2], bw[3]);
                }
            }
            if (more) {
                float2 fpa0 = u2f2(pa0), fqa0 = u2f2(qa0), fpa1 = u2f2(pa1), fqa1 = u2f2(qa1);
                float2 fpb0 = u2f2(pb0), fqb0 = u2f2(qb0), fpb1 = u2f2(pb1), fqb1 = u2f2(qb1);
                float h00 = fmaxf(A1[0] + fpa0.x + fqa0.x, 0.f);
                float h01 = fmaxf(A1[1] + fpa0.y + fqa0.y, 0.f);
                float h10 = fmaxf(A1[2] + fpb0.x + fqb0.x, 0.f);
                float h11 = fmaxf(A1[3] + fpb0.y + fqb0.y, 0.f);
                float h02 = fmaxf(B1[0] + fpa1.x + fqa1.x, 0.f);
                float h03 = fmaxf(B1[1] + fpa1.y + fqa1.y, 0.f);
                float h12 = fmaxf(B1[2] + fpb1.x + fqb1.x, 0.f);
                float h13 = fmaxf(B1[3] + fpb1.y + fqb1.y, 0.f);
                float2 wlo = *(const float2*)&s_w20[16 * (j + 1) + 2 * tt];
                float2 whi = *(const float2*)&s_w20[16 * (j + 1) + 8 + 2 * tt];
                ggl = fmaf(h00, wlo.x, fmaf(h01, wlo.y, fmaf(h02, whi.x, fmaf(h03, whi.y, ggl))));
                ggh = fmaf(h10, wlo.x, fmaf(h11, wlo.y, fmaf(h12, whi.x, fmaf(h13, whi.y, ggh))));
                hf0 = f22h2u(h00, h01); hf1 = f22h2u(h10, h11);
                hf2 = f22h2u(h02, h03); hf3 = f22h2u(h12, h13);
                if (j < 22) {
                    int c0 = 16 * (j + 2) + 2 * tt, c1 = c0 + 8;
                    pa0 = __ldg((const uint32_t*)(Pa + c0));
                    pa1 = __ldg((const uint32_t*)(Pa + c1));
                    qa0 = __ldg((const uint32_t*)(Qa + c0));
                    qa1 = __ldg((const uint32_t*)(Qa + c1));
                    pb0 = __ldg((const uint32_t*)(Pb + c0));
                    pb1 = __ldg((const uint32_t*)(Pb + c1));
                    qb0 = __ldg((const uint32_t*)(Qb + c0));
                    qb1 = __ldg((const uint32_t*)(Qb + c1));
                }
            }
        }

        // ---- gate finalize ----
        ggl += __shfl_xor_sync(0xffffffffu, ggl, 1);
        ggl += __shfl_xor_sync(0xffffffffu, ggl, 2);
        ggh += __shfl_xor_sync(0xffffffffu, ggh, 1);
        ggh += __shfl_xor_sync(0xffffffffu, ggh, 2);
        float gl = 1.f / (1.f + expf(-(ggl + b20)));
        float gh = 1.f / (1.f + expf(-(ggh + b20)));

        // ---- output epilogue ----
        float* outa = out + (size_t)(e0 + ra) * DOUT;
        float* outb = out + (size_t)(e0 + rb) * DOUT;
#pragma unroll
        for (int jj = 0; jj < 16; jj++) {
            int col = 8 * jj + 2 * tt;
            float2 cc = __ldg((const float2*)&g_c0[col]);
            float2 bb = __ldg((const float2*)&b3[col]);
            float2 o0, o1;
            o0.x = fmaf(gl, acc2[jj][0] + cc.x, bb.x);
            o0.y = fmaf(gl, acc2[jj][1] + cc.y, bb.y);
            o1.x = fmaf(gh, acc2[jj][2] + cc.x, bb.x);
            o1.y = fmaf(gh, acc2[jj][3] + cc.y, bb.y);
            *(float2*)(outa + col) = o0;
            *(float2*)(outb + col) = o1;
        }
    }
}

// ---------------- launch ----------------
extern "C" void kernel_launch(void* const* d_in, const int* in_sizes, int n_in,
                              void* d_out, int out_size) {
    const float* vc  = (const float*)d_in[0];
    const float* ve1 = (const float*)d_in[1];
    const float* ve2 = (const float*)d_in[2];
    const int*   src = (const int*)  d_in[3];
    const int*   dst = (const int*)  d_in[4];
    const float* W1  = (const float*)d_in[5];
    const float* b1  = (const float*)d_in[6];
    const float* W2  = (const float*)d_in[7];
    const float* b2  = (const float*)d_in[8];
    const float* W3  = (const float*)d_in[9];
    const float* b3  = (const float*)d_in[10];
    float* out = (float*)d_out;

    cudaFuncSetAttribute(k_pq2,   cudaFuncAttributeMaxDynamicSharedMemorySize, PQ_SMEM);
    cudaFuncSetAttribute(k_fused, cudaFuncAttributeMaxDynamicSharedMemorySize, SMEM_F);

    k_w23 <<<HID, 128>>>(W2, W3);
    k_misc<<<1, 512>>>(W2, b2, W3);
    k_pq2 <<<148, 256, PQ_SMEM>>>(vc, W1, b1);
    k_fused<<<148, 256, SMEM_F>>>(ve1, ve2, src, dst, W1, b3, out);
}

// round 14
// speedup vs baseline: 2.0978x; 1.0833x over previous
#include <cuda_runtime.h>
#include <cuda_fp16.h>
#include <math.h>
#include <stdint.h>

#define N_NODES 50000
#define N_EDGES 800000
#define HID     384
#define DOUT    128
#define TME     128                 // edges per tile
#define NT      (N_EDGES / TME)     // 6250
#define NTPQ    ((N_NODES + 127) / 128)   // 391 node tiles

// ---------------- device scratch ----------------
__device__ __half g_P16[(size_t)N_NODES * HID];   // vc @ W1[0:128]        (fp16)
__device__ __half g_Q16[(size_t)N_NODES * HID];   // vc @ W1[128:256] + b1 (fp16)
__device__ float  g_W23[HID * DOUT];              // W2[:,1:] @ W3
__device__ float  g_w20[HID];                     // W2[:,0]
__device__ float  g_c0[DOUT];                     // b2[1:] @ W3
__device__ float  g_b20;                          // b2[0]

// ---------------- helpers ----------------
__device__ __forceinline__ void mma_f16(float c[4],
        uint32_t a0, uint32_t a1, uint32_t a2, uint32_t a3,
        uint32_t b0, uint32_t b1) {
    asm volatile("mma.sync.aligned.m16n8k16.row.col.f32.f16.f16.f32 "
        "{%0,%1,%2,%3}, {%4,%5,%6,%7}, {%8,%9}, {%0,%1,%2,%3};"
        : "+f"(c[0]), "+f"(c[1]), "+f"(c[2]), "+f"(c[3])
        : "r"(a0), "r"(a1), "r"(a2), "r"(a3), "r"(b0), "r"(b1));
}
__device__ __forceinline__ void ldsm_x4(uint32_t r[4], uint32_t addr) {
    asm volatile("ldmatrix.sync.aligned.m8n8.x4.shared.b16 {%0,%1,%2,%3}, [%4];"
        : "=r"(r[0]), "=r"(r[1]), "=r"(r[2]), "=r"(r[3]) : "r"(addr));
}
__device__ __forceinline__ uint32_t f22h2u(float a, float b) {
    __half2 h = __floats2half2_rn(a, b);
    return *reinterpret_cast<uint32_t*>(&h);
}
__device__ __forceinline__ float2 u2f2(uint32_t u) {
    __half2 h = *reinterpret_cast<__half2*>(&u);
    return __half22float2(h);
}
__device__ __forceinline__ uint32_t smem_u32(const void* p) {
    uint32_t a;
    asm("{ .reg .u64 t; cvta.to.shared.u64 t, %1; cvt.u32.u64 %0, t; }" : "=r"(a) : "l"(p));
    return a;
}

// ---------------- k_w23b: W23 + c0 + w20 + b20 in one launch ----------------
__global__ void k_w23b(const float* __restrict__ W2, const float* __restrict__ W3,
                       const float* __restrict__ b2) {
    int b = blockIdx.x, t = threadIdx.x;   // block = 128
    if (b < HID) {
        __shared__ float s[512];
        for (int j = t; j < 512; j += 128) s[j] = W2[b * 513 + 1 + j];
        __syncthreads();
        float a0 = 0.f, a1 = 0.f, a2 = 0.f, a3 = 0.f;
#pragma unroll 4
        for (int j = 0; j < 512; j += 4) {
            a0 = fmaf(s[j],     W3[(j)     * DOUT + t], a0);
            a1 = fmaf(s[j + 1], W3[(j + 1) * DOUT + t], a1);
            a2 = fmaf(s[j + 2], W3[(j + 2) * DOUT + t], a2);
            a3 = fmaf(s[j + 3], W3[(j + 3) * DOUT + t], a3);
        }
        g_W23[b * DOUT + t] = (a0 + a1) + (a2 + a3);
    } else if (b == HID) {
        float a0 = 0.f, a1 = 0.f, a2 = 0.f, a3 = 0.f;
#pragma unroll 4
        for (int j = 0; j < 512; j += 4) {
            a0 = fmaf(b2[1 + j],     W3[(j)     * DOUT + t], a0);
            a1 = fmaf(b2[2 + j],     W3[(j + 1) * DOUT + t], a1);
            a2 = fmaf(b2[3 + j],     W3[(j + 2) * DOUT + t], a2);
            a3 = fmaf(b2[4 + j],     W3[(j + 3) * DOUT + t], a3);
        }
        g_c0[t] = (a0 + a1) + (a2 + a3);
        if (t == 0) g_b20 = b2[0];
    } else {
        for (int i = t; i < HID; i += 128) g_w20[i] = W2[i * 513];
    }
}

// ---------------- k_pq2: node GEMM, persistent, fp16 mma ----------------
#define PQ_SMX  0
#define PQ_SMW  32768
#define PQ_SMEM (32768 + 2 * 98304)   // 229376

__global__ void __launch_bounds__(256, 1) k_pq2(const float* __restrict__ vc,
                                                const float* __restrict__ W1,
                                                const float* __restrict__ b1) {
    extern __shared__ __align__(16) char smem[];
    uint32_t* s_x = (uint32_t*)(smem + PQ_SMX);
    uint32_t* s_w = (uint32_t*)(smem + PQ_SMW);

    int t = threadIdx.x;
    int warp = t >> 5, lane = t & 31;
    int wm = warp;
    int g = lane >> 2, tt = lane & 3;

    for (int i = t; i < 2 * 384 * 64; i += 256) {
        int half = i / (384 * 64), r = i - half * 384 * 64;
        int n = r >> 6, w = r & 63;
        int k = 2 * w;
        s_w[half * 24576 + (n << 6) + (w ^ ((n & 7) << 2))] =
            f22h2u(W1[(size_t)(half * 128 + k) * HID + n],
                   W1[(size_t)(half * 128 + k + 1) * HID + n]);
    }

    int arow_off = ((lane >> 3) & 1) * 8 + (lane & 7);
    uint32_t wsel_a = (uint32_t)(((lane >> 4) & 1) * 4);
    int nrow_off = ((lane >> 4) & 1) * 8 + (lane & 7);
    uint32_t wsel_b = (uint32_t)(((lane >> 3) & 1) * 4);
    uint32_t slxB = (uint32_t)(nrow_off & 7) << 2;

    uint32_t sxu = smem_u32(smem + PQ_SMX);
    uint32_t swu = smem_u32(smem + PQ_SMW);
    int ar = wm * 16 + arow_off;
    uint32_t aswz = (uint32_t)(ar & 7) << 2;
    uint32_t a_base = sxu + ((uint32_t)ar << 8);
    uint32_t w_lane = swu + ((uint32_t)nrow_off << 8);
    int ra_off = wm * 16 + g;
    __syncthreads();

    for (int tile = blockIdx.x; tile < NTPQ; tile += gridDim.x) {
        int n0 = tile * 128;
        __syncthreads();
#pragma unroll
        for (int p = 0; p < 8; p++) {
            int xr = p * 16 + (t >> 4);
            int i  = t & 15;
            int node = n0 + xr; if (node >= N_NODES) node = N_NODES - 1;
            uint32_t rs = (uint32_t)xr << 6;
            uint32_t sw = (uint32_t)(xr & 7) << 2;
            float4 v1 = __ldg((const float4*)(vc + (size_t)node * 128) + i);
            *(uint2*)&s_x[rs + (((uint32_t)(2 * i)) ^ sw)] =
                make_uint2(f22h2u(v1.x, v1.y), f22h2u(v1.z, v1.w));
            float4 v2 = __ldg((const float4*)(vc + (size_t)node * 128) + 16 + i);
            *(uint2*)&s_x[rs + (((uint32_t)(32 + 2 * i)) ^ sw)] =
                make_uint2(f22h2u(v2.x, v2.y), f22h2u(v2.z, v2.w));
        }
        __syncthreads();

        uint32_t areg[8][4];
#pragma unroll
        for (int ks = 0; ks < 8; ks++)
            ldsm_x4(areg[ks], a_base + 4u * (((uint32_t)(8 * ks) + wsel_a) ^ aswz));

        int ra = n0 + ra_off, rb = ra + 8;
#pragma unroll 1
        for (int half = 0; half < 2; half++) {
            __half* dstp = half ? g_Q16 : g_P16;
            uint32_t wl = w_lane + (uint32_t)half * 98304u;
#pragma unroll 1
            for (int j = 0; j < 24; j++) {
                float A1[4] = {0.f, 0.f, 0.f, 0.f};
                float B1[4] = {0.f, 0.f, 0.f, 0.f};
                uint32_t wbase = wl + ((uint32_t)j << 12);
#pragma unroll
                for (int ks = 0; ks < 8; ks++) {
                    uint32_t bw[4];
                    ldsm_x4(bw, wbase + 4u * (((uint32_t)(8 * ks) + wsel_b) ^ slxB));
                    mma_f16(A1, areg[ks][0], areg[ks][1], areg[ks][2], areg[ks][3], bw[0], bw[1]);
                    mma_f16(B1, areg[ks][0], areg[ks][1], areg[ks][2], areg[ks][3], bw[2], bw[3]);
                }
                float2 blo = make_float2(0.f, 0.f), bhi = make_float2(0.f, 0.f);
                if (half) {
                    blo = __ldg((const float2*)&b1[16 * j + 2 * tt]);
                    bhi = __ldg((const float2*)&b1[16 * j + 8 + 2 * tt]);
                }
                if (ra < N_NODES) {
                    *(uint32_t*)&dstp[(size_t)ra * HID + 16 * j + 2 * tt] =
                        f22h2u(A1[0] + blo.x, A1[1] + blo.y);
                    *(uint32_t*)&dstp[(size_t)ra * HID + 16 * j + 8 + 2 * tt] =
                        f22h2u(B1[0] + bhi.x, B1[1] + bhi.y);
                }
                if (rb < N_NODES) {
                    *(uint32_t*)&dstp[(size_t)rb * HID + 16 * j + 2 * tt] =
                        f22h2u(A1[2] + blo.x, A1[3] + blo.y);
                    *(uint32_t*)&dstp[(size_t)rb * HID + 16 * j + 8 + 2 * tt] =
                        f22h2u(B1[2] + bhi.x, B1[3] + bhi.y);
                }
            }
        }
    }
}

// ---------------- k_fused: 8 warps x m16; h in regs; depth-2 P/Q prefetch ----------------
#define SM_SRC  0
#define SM_DST  512
#define SM_W20  1024
#define SM_X    2560
#define SM_WVE  35328
#define SM_W23  133632
#define SMEM_F  231936

// prefetch P/Q fragments of chunk J2 into register set S
#define PQ_PREF(J2, S) do { \
    int c0_ = 16 * (J2) + 2 * tt, c1_ = c0_ + 8; \
    pa0##S = __ldg((const uint32_t*)(Pa + c0_)); \
    pa1##S = __ldg((const uint32_t*)(Pa + c1_)); \
    qa0##S = __ldg((const uint32_t*)(Qa + c0_)); \
    qa1##S = __ldg((const uint32_t*)(Qa + c1_)); \
    pb0##S = __ldg((const uint32_t*)(Pb + c0_)); \
    pb1##S = __ldg((const uint32_t*)(Pb + c1_)); \
    qb0##S = __ldg((const uint32_t*)(Qb + c0_)); \
    qb1##S = __ldg((const uint32_t*)(Qb + c1_)); \
} while (0)

// one n16 chunk: GEMM1 -> epilogue (uses pq set S) -> prefetch J+2 into S -> GEMM2
#define CHUNK(J, S) do { \
    float A1[4] = {0.f, 0.f, 0.f, 0.f}, B1[4] = {0.f, 0.f, 0.f, 0.f}; \
    uint32_t wbase_ = wve_lane + ((uint32_t)(J) << 12); \
    _Pragma("unroll") \
    for (int ks = 0; ks < 8; ks++) { \
        uint32_t bw_[4]; \
        ldsm_x4(bw_, wbase_ + 4u * (((uint32_t)(8 * ks) + wsel_b) ^ slxB)); \
        mma_f16(A1, areg[ks][0], areg[ks][1], areg[ks][2], areg[ks][3], bw_[0], bw_[1]); \
        mma_f16(B1, areg[ks][0], areg[ks][1], areg[ks][2], areg[ks][3], bw_[2], bw_[3]); \
    } \
    float2 fpa0 = u2f2(pa0##S), fqa0 = u2f2(qa0##S); \
    float2 fpa1 = u2f2(pa1##S), fqa1 = u2f2(qa1##S); \
    float2 fpb0 = u2f2(pb0##S), fqb0 = u2f2(qb0##S); \
    float2 fpb1 = u2f2(pb1##S), fqb1 = u2f2(qb1##S); \
    float h00 = fmaxf(A1[0] + fpa0.x + fqa0.x, 0.f); \
    float h01 = fmaxf(A1[1] + fpa0.y + fqa0.y, 0.f); \
    float h10 = fmaxf(A1[2] + fpb0.x + fqb0.x, 0.f); \
    float h11 = fmaxf(A1[3] + fpb0.y + fqb0.y, 0.f); \
    float h02 = fmaxf(B1[0] + fpa1.x + fqa1.x, 0.f); \
    float h03 = fmaxf(B1[1] + fpa1.y + fqa1.y, 0.f); \
    float h12 = fmaxf(B1[2] + fpb1.x + fqb1.x, 0.f); \
    float h13 = fmaxf(B1[3] + fpb1.y + fqb1.y, 0.f); \
    float2 wlo = *(const float2*)&s_w20[16 * (J) + 2 * tt]; \
    float2 whi = *(const float2*)&s_w20[16 * (J) + 8 + 2 * tt]; \
    ggl = fmaf(h00, wlo.x, fmaf(h01, wlo.y, fmaf(h02, whi.x, fmaf(h03, whi.y, ggl)))); \
    ggh = fmaf(h10, wlo.x, fmaf(h11, wlo.y, fmaf(h12, whi.x, fmaf(h13, whi.y, ggh)))); \
    uint32_t hf0 = f22h2u(h00, h01), hf1 = f22h2u(h10, h11); \
    uint32_t hf2 = f22h2u(h02, h03), hf3 = f22h2u(h12, h13); \
    if ((J) < 22) PQ_PREF((J) + 2, S); \
    uint32_t w2base_ = w23_lane + 4u * (((uint32_t)(8 * (J)) + wsel_b) ^ slxB); \
    _Pragma("unroll") \
    for (int jj = 0; jj < 8; jj++) { \
        uint32_t b2_[4]; \
        ldsm_x4(b2_, w2base_ + (uint32_t)jj * 12288u); \
        mma_f16(acc2[2 * jj],     hf0, hf1, hf2, hf3, b2_[0], b2_[1]); \
        mma_f16(acc2[2 * jj + 1], hf0, hf1, hf2, hf3, b2_[2], b2_[3]); \
    } \
} while (0)

__global__ void __launch_bounds__(256, 1) k_fused(
    const float* __restrict__ ve1, const float* __restrict__ ve2,
    const int*   __restrict__ src, const int* __restrict__ dst,
    const float* __restrict__ W1,  const float* __restrict__ b3,
    float* __restrict__ out)
{
    extern __shared__ __align__(16) char smem[];
    int*      s_src = (int*)(smem + SM_SRC);
    int*      s_dst = (int*)(smem + SM_DST);
    float*    s_w20 = (float*)(smem + SM_W20);
    uint32_t* s_x   = (uint32_t*)(smem + SM_X);
    uint32_t* s_wve = (uint32_t*)(smem + SM_WVE);
    uint32_t* s_w23 = (uint32_t*)(smem + SM_W23);

    int t = threadIdx.x;
    int warp = t >> 5, lane = t & 31;
    int wm = warp;
    int g = lane >> 2, tt = lane & 3;

    for (int i = t; i < 384 * 64; i += 256) {
        int n = i >> 6, w = i & 63;
        int k = 2 * w;
        s_wve[(n << 6) + (w ^ ((n & 7) << 2))] =
            f22h2u(W1[(size_t)(256 + k) * HID + n], W1[(size_t)(257 + k) * HID + n]);
    }
    for (int i = t; i < 128 * 192; i += 256) {
        int n = i / 192, w = i - n * 192;
        int k = 2 * w;
        s_w23[n * 192 + (w ^ ((n & 7) << 2))] =
            f22h2u(g_W23[(size_t)k * DOUT + n], g_W23[(size_t)(k + 1) * DOUT + n]);
    }
    for (int i = t; i < HID; i += 256) s_w20[i] = g_w20[i];
    float b20 = g_b20;

    int arow_off = ((lane >> 3) & 1) * 8 + (lane & 7);
    uint32_t wsel_a = (uint32_t)(((lane >> 4) & 1) * 4);
    int nrow_off = ((lane >> 4) & 1) * 8 + (lane & 7);
    uint32_t wsel_b = (uint32_t)(((lane >> 3) & 1) * 4);
    uint32_t slxB = (uint32_t)(nrow_off & 7) << 2;

    uint32_t sxu  = smem_u32(smem + SM_X);
    uint32_t wveu = smem_u32(smem + SM_WVE);
    uint32_t w23u = smem_u32(smem + SM_W23);
    int ar = wm * 16 + arow_off;
    uint32_t aswz = (uint32_t)(ar & 7) << 2;
    uint32_t a_base = sxu + ((uint32_t)ar << 8);
    uint32_t wve_lane = wveu + ((uint32_t)nrow_off << 8);
    uint32_t w23_lane = w23u + (uint32_t)nrow_off * 768u;

    int ra = wm * 16 + g, rb = ra + 8;

    for (int tile = blockIdx.x; tile < NT; tile += gridDim.x) {
        int e0 = tile * TME;
        __syncthreads();

        if (t < 128) s_src[t] = src[e0 + t];
        else s_dst[t - 128] = dst[e0 + t - 128];
#pragma unroll
        for (int p = 0; p < 8; p++) {
            int xr = p * 16 + (t >> 4);
            int i  = t & 15;
            uint32_t rs = (uint32_t)xr << 6;
            uint32_t sw = (uint32_t)(xr & 7) << 2;
            float4 v1 = __ldg((const float4*)(ve1 + (size_t)(e0 + xr) * 64) + i);
            *(uint2*)&s_x[rs + (((uint32_t)(2 * i)) ^ sw)] =
                make_uint2(f22h2u(v1.x, v1.y), f22h2u(v1.z, v1.w));
            float4 v2 = __ldg((const float4*)(ve2 + (size_t)(e0 + xr) * 64) + i);
            *(uint2*)&s_x[rs + (((uint32_t)(32 + 2 * i)) ^ sw)] =
                make_uint2(f22h2u(v2.x, v2.y), f22h2u(v2.z, v2.w));
        }
        __syncthreads();

        uint32_t areg[8][4];
#pragma unroll
        for (int ks = 0; ks < 8; ks++)
            ldsm_x4(areg[ks], a_base + 4u * (((uint32_t)(8 * ks) + wsel_a) ^ aswz));

        const __half* Pa = g_P16 + (size_t)s_src[ra] * HID;
        const __half* Qa = g_Q16 + (size_t)s_dst[ra] * HID;
        const __half* Pb = g_P16 + (size_t)s_src[rb] * HID;
        const __half* Qb = g_Q16 + (size_t)s_dst[rb] * HID;

        float acc2[16][4];
#pragma unroll
        for (int j = 0; j < 16; j++)
#pragma unroll
            for (int i = 0; i < 4; i++) acc2[j][i] = 0.f;
        float ggl = 0.f, ggh = 0.f;

        // depth-2 prefetch ring: set A = even chunks, set B = odd chunks
        uint32_t pa0A, pa1A, qa0A, qa1A, pb0A, pb1A, qb0A, qb1A;
        uint32_t pa0B, pa1B, qa0B, qa1B, pb0B, pb1B, qb0B, qb1B;
        PQ_PREF(0, A);
        PQ_PREF(1, B);

#pragma unroll 1
        for (int j2 = 0; j2 < 12; j2++) {
            int j = 2 * j2;
            CHUNK(j, A);
            CHUNK(j + 1, B);
        }

        // ---- gate finalize ----
        ggl += __shfl_xor_sync(0xffffffffu, ggl, 1);
        ggl += __shfl_xor_sync(0xffffffffu, ggl, 2);
        ggh += __shfl_xor_sync(0xffffffffu, ggh, 1);
        ggh += __shfl_xor_sync(0xffffffffu, ggh, 2);
        float gl = 1.f / (1.f + expf(-(ggl + b20)));
        float gh = 1.f / (1.f + expf(-(ggh + b20)));

        // ---- output epilogue ----
        float* outa = out + (size_t)(e0 + ra) * DOUT;
        float* outb = out + (size_t)(e0 + rb) * DOUT;
#pragma unroll
        for (int jj = 0; jj < 16; jj++) {
            int col = 8 * jj + 2 * tt;
            float2 cc = __ldg((const float2*)&g_c0[col]);
            float2 bb = __ldg((const float2*)&b3[col]);
            float2 o0, o1;
            o0.x = fmaf(gl, acc2[jj][0] + cc.x, bb.x);
            o0.y = fmaf(gl, acc2[jj][1] + cc.y, bb.y);
            o1.x = fmaf(gh, acc2[jj][2] + cc.x, bb.x);
            o1.y = fmaf(gh, acc2[jj][3] + cc.y, bb.y);
            *(float2*)(outa + col) = o0;
            *(float2*)(outb + col) = o1;
        }
    }
}

// ---------------- launch ----------------
extern "C" void kernel_launch(void* const* d_in, const int* in_sizes, int n_in,
                              void* d_out, int out_size) {
    const float* vc  = (const float*)d_in[0];
    const float* ve1 = (const float*)d_in[1];
    const float* ve2 = (const float*)d_in[2];
    const int*   src = (const int*)  d_in[3];
    const int*   dst = (const int*)  d_in[4];
    const float* W1  = (const float*)d_in[5];
    const float* b1  = (const float*)d_in[6];
    const float* W2  = (const float*)d_in[7];
    const float* b2  = (const float*)d_in[8];
    const float* W3  = (const float*)d_in[9];
    const float* b3  = (const float*)d_in[10];
    float* out = (float*)d_out;

    cudaFuncSetAttribute(k_pq2,   cudaFuncAttributeMaxDynamicSharedMemorySize, PQ_SMEM);
    cudaFuncSetAttribute(k_fused, cudaFuncAttributeMaxDynamicSharedMemorySize, SMEM_F);

    k_w23b<<<HID + 2, 128>>>(W2, W3, b2);
    k_pq2 <<<148, 256, PQ_SMEM>>>(vc, W1, b1);
    k_fused<<<148, 256, SMEM_F>>>(ve1, ve2, src, dst, W1, b3, out);
}